// round 11
// baseline (speedup 1.0000x reference)
#include <cuda_runtime.h>
#include <cuda_fp16.h>
#include <cstdint>
#include <cfloat>

#define N_ROWS   262144
#define K_CENT   256
#define D_DIM    64
#define NUM_CLS  10
#define TILE_M   128
#define N_TILES  (N_ROWS / TILE_M)   /* 2048 */
#define GRID_X   296                 /* 2 CTAs/SM * 148 SMs */
#define NTHREADS 256
#define A_STRIDE 2368                /* 16*144 chunk area + 64 x2 */

// ---------------- device-global scratch (zero at module load; last CTA re-zeros) --
__device__ double g_loss;                       // = 0.0
__device__ int    g_counts[NUM_CLS * NUM_CLS];  // = {0}
__device__ unsigned int g_done;                 // = 0

// ---------------- helpers ----------------
__device__ __forceinline__ uint32_t h2(float a, float b) {
    __half2 h = __floats2half2_rn(a, b);
    return *reinterpret_cast<uint32_t*>(&h);
}

__device__ __forceinline__ void mma_f16(float& d0, float& d1, float& d2, float& d3,
                                        uint32_t a0, uint32_t a1, uint32_t a2, uint32_t a3,
                                        uint32_t b0, uint32_t b1) {
    asm("mma.sync.aligned.m16n8k16.row.col.f32.f16.f16.f32 "
        "{%0,%1,%2,%3}, {%4,%5,%6,%7}, {%8,%9}, {%0,%1,%2,%3};"
        : "+f"(d0), "+f"(d1), "+f"(d2), "+f"(d3)
        : "r"(a0), "r"(a1), "r"(a2), "r"(a3), "r"(b0), "r"(b1));
}

// argmin key: truncate e mantissa low bits, pack col into low byte (ties -> lower col)
__device__ __forceinline__ uint32_t akey(float e, int col) {
    return (__float_as_uint(e) & 0xFFFFFF00u) | (uint32_t)col;
}

struct SmemLayout {
    uint4 B[K_CENT * 8];            // 32 KB  (B' = -2*c fp16 fragments, XOR-swizzled)
    float c2[K_CENT];               // c2[n] + 1
    unsigned char A[8 * A_STRIDE];  // per-warp staged A slices (fp16, padded layout)
};

__global__ __launch_bounds__(NTHREADS, 2)
void kmeans_hmma_kernel(const float* __restrict__ x,
                        const int*   __restrict__ y32,
                        const float* __restrict__ centers,
                        float* __restrict__ out) {
    extern __shared__ unsigned char s_raw[];
    SmemLayout* sm = reinterpret_cast<SmemLayout*>(s_raw);
    __shared__ int    s_hist[NUM_CLS * NUM_CLS];
    __shared__ double s_loss;
    __shared__ int    s_y_is32;
    __shared__ int    s_is_last;

    const int tid  = threadIdx.x;
    const int wid  = tid >> 5;
    const int lane = tid & 31;
    const int g    = lane >> 2;   // consumer: row within mma row-group (0..7)
    const int t4   = lane & 3;
    const int r    = lane >> 1;   // producer: row 0..15 in warp slice
    const int h    = lane & 1;    // producer: which 32-float half of the row

    unsigned char* As_w = sm->A + wid * A_STRIDE;

    if (tid < NUM_CLS * NUM_CLS) s_hist[tid] = 0;
    if (tid == 0) s_loss = 0.0;
    // label dtype probe: int64 LE -> odd 32-bit words are all 0
    if (wid == 0) {
        int v = (y32[2 * (lane * 7 + 1) + 1] != 0) | (y32[2 * (lane + 64) + 1] != 0);
        uint32_t any = __ballot_sync(0xFFFFFFFFu, v);
        if (lane == 0) s_y_is32 = (any != 0);
    }

    // ---- build fp16 B' = -2*c fragments in smem, once per CTA ----
    for (int w = tid; w < K_CENT * 8; w += NTHREADS) {
        int n   = w >> 3;
        int u8  = w & 7;
        int kcp = u8 >> 2, tt = u8 & 3;
        const float* cn = centers + n * D_DIM;
        int kb0 = (2 * kcp) * 16 + tt * 2;
        int kb1 = kb0 + 16;
        float2 p00 = *(const float2*)(cn + kb0);
        float2 p01 = *(const float2*)(cn + kb0 + 8);
        float2 p10 = *(const float2*)(cn + kb1);
        float2 p11 = *(const float2*)(cn + kb1 + 8);
        int u = u8 ^ ((n & 1) << 2);
        sm->B[n * 8 + u] = make_uint4(h2(-2.f * p00.x, -2.f * p00.y),
                                      h2(-2.f * p01.x, -2.f * p01.y),
                                      h2(-2.f * p10.x, -2.f * p10.y),
                                      h2(-2.f * p11.x, -2.f * p11.y));
    }
    // center norms + 1 (fp32 exact)
    if (tid < K_CENT) {
        const float4* cp = (const float4*)(centers + tid * D_DIM);
        float a = 0.f;
        #pragma unroll
        for (int j = 0; j < 16; j++) {
            float4 v = cp[j];
            a = fmaf(v.x, v.x, a); a = fmaf(v.y, v.y, a);
            a = fmaf(v.z, v.z, a); a = fmaf(v.w, v.w, a);
        }
        sm->c2[tid] = a + 1.0f;
    }
    __syncthreads();
    const int y_is32 = s_y_is32;

    const uint4* Bbase = sm->B + g * 8;
    const int    uswz  = (g & 1) << 2;
    unsigned char* dst = As_w + r * 144 + h * 16;   // producer chunk base

    // convert+store one float4 (floats 4s..4s+3 of this thread's half-row)
    // unit u=16h+2s -> chunk slot ((2s)&3)*2+h, pos s>>1 ; likewise u+1
    float p_nrm = 0.f;
    auto cvst = [&](const float4& v, int s) {
        p_nrm = fmaf(v.x, v.x, fmaf(v.y, v.y, fmaf(v.z, v.z, fmaf(v.w, v.w, p_nrm))));
        *(uint32_t*)(dst + (((2 * s) & 3) * 32)     + ((s >> 1) * 4)) = h2(v.x, v.y);
        *(uint32_t*)(dst + (((2 * s + 1) & 3) * 32) + ((s >> 1) * 4)) = h2(v.z, v.w);
    };

    // ---- prime: stage tile blockIdx.x into this warp's slice ----
    {
        int rowp = blockIdx.x * TILE_M + wid * 16 + r;
        const float4* xn = (const float4*)(x + (size_t)rowp * D_DIM) + h * 8;
        p_nrm = 0.f;
        #pragma unroll
        for (int s = 0; s < 8; s++) cvst(xn[s], s);
        p_nrm += __shfl_xor_sync(0xFFFFFFFFu, p_nrm, 1);
        if (h == 0) *(float*)(As_w + 2304 + r * 4) = p_nrm;
    }
    __syncwarp();

    float loss_local = 0.f;

    for (int t = blockIdx.x; t < N_TILES; t += GRID_X) {
        __syncwarp();
        // ---- consume staged A: 4 conflict-free LDS.128 + 2 broadcast LDS.32 ----
        const unsigned char* Ard0 = As_w + g * 144 + t4 * 32;
        const unsigned char* Ard1 = As_w + (g + 8) * 144 + t4 * 32;
        uint4 ch0 = *(const uint4*)(Ard0);        // ah[0][0] ah[0][2] ah[1][0] ah[1][2]
        uint4 ch1 = *(const uint4*)(Ard0 + 16);   // ah[2][0] ah[2][2] ah[3][0] ah[3][2]
        uint4 ch2 = *(const uint4*)(Ard1);        // ah[0][1] ah[0][3] ah[1][1] ah[1][3]
        uint4 ch3 = *(const uint4*)(Ard1 + 16);   // ah[2][1] ah[2][3] ah[3][1] ah[3][3]
        const float x2a = *(const float*)(As_w + 2304 + g * 4);
        const float x2b = *(const float*)(As_w + 2304 + (g + 8) * 4);

        // ---- producer state for next tile (address clamped on last iteration) ----
        int tn = t + GRID_X;
        int rowp = ((tn < N_TILES) ? tn : t) * TILE_M + wid * 16 + r;
        const float4* xn = (const float4*)(x + (size_t)rowp * D_DIM) + h * 8;
        float4 pfa, pfb;
        p_nrm = 0.f;

        float sw0 = 0.f, swe0 = 0.f, sw1 = 0.f, swe1 = 0.f;
        float dmin0 = FLT_MAX, dmin1 = FLT_MAX;
        float dmin10_0 = FLT_MAX, dmin10_1 = FLT_MAX;
        uint32_t key10_0 = 0xFFFFFFFFu, key10_1 = 0xFFFFFFFFu;

        const int r0 = t * TILE_M + wid * 16 + g;   // consumer rows r0, r0+8

        #pragma unroll
        for (int ng = 0; ng < 32; ng++) {
            // producer: issue next-tile loads early, convert ~2 groups later
            if (ng == 0 || ng == 3 || ng == 6 || ng == 9) {
                int i = ng / 3;
                pfa = xn[2 * i]; pfb = xn[2 * i + 1];
            }

            const uint4* Bn = Bbase + ng * 64;
            uint4 bv0 = Bn[(0 + t4) ^ uswz];     // k-chunks 0,1
            uint4 bv1 = Bn[(4 + t4) ^ uswz];     // k-chunks 2,3
            float2 c2p = *(const float2*)(sm->c2 + ng * 8 + t4 * 2);
            float a0 = x2a + c2p.x, a1 = x2a + c2p.y;
            float a2 = x2b + c2p.x, a3 = x2b + c2p.y;
            mma_f16(a0, a1, a2, a3, ch0.x, ch2.x, ch0.y, ch2.y, bv0.x, bv0.y);
            mma_f16(a0, a1, a2, a3, ch0.z, ch2.z, ch0.w, ch2.w, bv0.z, bv0.w);
            mma_f16(a0, a1, a2, a3, ch1.x, ch3.x, ch1.y, ch3.y, bv1.x, bv1.y);
            mma_f16(a0, a1, a2, a3, ch1.z, ch3.z, ch1.w, ch3.w, bv1.z, bv1.w);
            float w0 = __powf(a0, -0.1f);
            float w1 = __powf(a1, -0.1f);
            float w2 = __powf(a2, -0.1f);
            float w3 = __powf(a3, -0.1f);
            sw0 += w0 + w1;
            sw1 += w2 + w3;
            swe0 = fmaf(w0, a0, swe0); swe0 = fmaf(w1, a1, swe0);
            swe1 = fmaf(w2, a2, swe1); swe1 = fmaf(w3, a3, swe1);
            dmin0 = fminf(dmin0, fminf(a0, a1));
            dmin1 = fminf(dmin1, fminf(a2, a3));
            if (ng < 2) {
                // cols < 10 live only in ng=0 (cols 0-7) and ng=1/t4==0 (cols 8,9)
                if (ng == 0 || t4 == 0) {
                    const int cb = ng * 8 + t4 * 2;
                    key10_0 = min(key10_0, min(akey(a0, cb), akey(a1, cb + 1)));
                    key10_1 = min(key10_1, min(akey(a2, cb), akey(a3, cb + 1)));
                    dmin10_0 = fminf(dmin10_0, fminf(a0, a1));
                    dmin10_1 = fminf(dmin10_1, fminf(a2, a3));
                }
            }

            if (ng == 2 || ng == 5 || ng == 8 || ng == 11) {
                int i = (ng - 2) / 3;
                cvst(pfa, 2 * i); cvst(pfb, 2 * i + 1);
            }
            if (ng == 13) {
                p_nrm += __shfl_xor_sync(0xFFFFFFFFu, p_nrm, 1);
                if (h == 0) *(float*)(As_w + 2304 + r * 4) = p_nrm;
            }
        }

        // quad reduction (4 lanes cover all 256 cols of rows r0, r0+8)
        #pragma unroll
        for (int off = 1; off <= 2; off <<= 1) {
            sw0  += __shfl_xor_sync(0xFFFFFFFFu, sw0,  off);
            swe0 += __shfl_xor_sync(0xFFFFFFFFu, swe0, off);
            sw1  += __shfl_xor_sync(0xFFFFFFFFu, sw1,  off);
            swe1 += __shfl_xor_sync(0xFFFFFFFFu, swe1, off);
            dmin0 = fminf(dmin0, __shfl_xor_sync(0xFFFFFFFFu, dmin0, off));
            dmin1 = fminf(dmin1, __shfl_xor_sync(0xFFFFFFFFu, dmin1, off));
            dmin10_0 = fminf(dmin10_0, __shfl_xor_sync(0xFFFFFFFFu, dmin10_0, off));
            dmin10_1 = fminf(dmin10_1, __shfl_xor_sync(0xFFFFFFFFu, dmin10_1, off));
            key10_0 = min(key10_0, __shfl_xor_sync(0xFFFFFFFFu, key10_0, off));
            key10_1 = min(key10_1, __shfl_xor_sync(0xFFFFFFFFu, key10_1, off));
        }

        if (t4 == 0) {
            loss_local += swe0 / sw0 + swe1 / sw1 - 2.0f;   // swe/sw - 1 per row
            // argmin < 10  <=>  min over cols<10 equals global min (ties -> lower col)
            if (dmin10_0 <= dmin0) {
                int lab = y_is32 ? y32[r0] : y32[2 * r0];
                atomicAdd_block(&s_hist[(int)(key10_0 & 0xFFu) * NUM_CLS + lab], 1);
            }
            if (dmin10_1 <= dmin1) {
                int r1 = r0 + 8;
                int lab = y_is32 ? y32[r1] : y32[2 * r1];
                atomicAdd_block(&s_hist[(int)(key10_1 & 0xFFu) * NUM_CLS + lab], 1);
            }
        }
    }

    // ---- flush per-CTA accumulators to global ----
    #pragma unroll
    for (int off = 16; off > 0; off >>= 1)
        loss_local += __shfl_xor_sync(0xFFFFFFFFu, loss_local, off);
    if (lane == 0) atomicAdd_block(&s_loss, (double)loss_local);
    __syncthreads();
    if (tid == 0) atomicAdd(&g_loss, s_loss);
    if (tid < NUM_CLS * NUM_CLS && s_hist[tid] > 0)
        atomicAdd(&g_counts[tid], s_hist[tid]);

    // ---- last-CTA fused finalize ----
    __threadfence();
    __syncthreads();
    if (tid == 0) {
        unsigned int prev = atomicAdd(&g_done, 1u);
        s_is_last = (prev == GRID_X - 1);
    }
    __syncthreads();
    if (!s_is_last || tid != 0) return;

    float counts[NUM_CLS * NUM_CLS];
    #pragma unroll
    for (int i = 0; i < NUM_CLS * NUM_CLS; i++)
        counts[i] = (float)atomicAdd(&g_counts[i], 0);

    bool used[NUM_CLS];
    #pragma unroll
    for (int i = 0; i < NUM_CLS; i++) used[i] = false;

    float correct = 0.f;
    for (int i = 0; i < NUM_CLS; i++) {
        const float* bin = &counts[i * NUM_CLS];
        float tot = 0.f;
        for (int j = 0; j < NUM_CLS; j++) tot += bin[j];
        int label = 0; float best = bin[0];
        for (int j = 1; j < NUM_CLS; j++)
            if (bin[j] > best) { best = bin[j]; label = j; }
        if (used[label]) {
            int l2 = 0; float b2 = used[0] ? 0.f : bin[0];
            for (int j = 1; j < NUM_CLS; j++) {
                float v = used[j] ? 0.f : bin[j];
                if (v > b2) { b2 = v; l2 = j; }
            }
            label = l2;
        }
        if (tot > 0.f) { correct += bin[label]; used[label] = true; }
    }
    out[0] = (float)g_loss;
    out[1] = correct / (float)N_ROWS;

    // reset globals so the next graph replay starts from a clean state
    g_loss = 0.0;
    #pragma unroll
    for (int i = 0; i < NUM_CLS * NUM_CLS; i++) g_counts[i] = 0;
    g_done = 0u;
}

// ---------------- launch ----------------
extern "C" void kernel_launch(void* const* d_in, const int* in_sizes, int n_in,
                              void* d_out, int out_size) {
    const float* x       = (const float*)d_in[0];
    const int*   y32     = (const int*)d_in[1];
    const float* centers = (const float*)d_in[2];

    const int dyn_smem = (int)sizeof(SmemLayout);
    cudaFuncSetAttribute(kmeans_hmma_kernel,
                         cudaFuncAttributeMaxDynamicSharedMemorySize, dyn_smem);

    kmeans_hmma_kernel<<<GRID_X, NTHREADS, dyn_smem>>>(x, y32, centers, (float*)d_out);
}

// round 12
// speedup vs baseline: 1.3344x; 1.3344x over previous
#include <cuda_runtime.h>
#include <cuda_fp16.h>
#include <cstdint>
#include <cfloat>

#define N_ROWS   262144
#define K_CENT   256
#define D_DIM    64
#define NUM_CLS  10
#define TILE_M   128
#define N_TILES  (N_ROWS / TILE_M)   /* 2048 */
#define GRID_X   296                 /* 2 CTAs/SM * 148 SMs */
#define NTHREADS 256

// ---------------- device-global scratch (zero at module load; last CTA re-zeros) --
__device__ double g_loss;                       // = 0.0
__device__ int    g_counts[NUM_CLS * NUM_CLS];  // = {0}
__device__ unsigned int g_done;                 // = 0

// ---------------- helpers ----------------
__device__ __forceinline__ uint32_t h2(float a, float b) {
    __half2 h = __floats2half2_rn(a, b);
    return *reinterpret_cast<uint32_t*>(&h);
}

__device__ __forceinline__ void mma_f16(float& d0, float& d1, float& d2, float& d3,
                                        uint32_t a0, uint32_t a1, uint32_t a2, uint32_t a3,
                                        uint32_t b0, uint32_t b1) {
    asm("mma.sync.aligned.m16n8k16.row.col.f32.f16.f16.f32 "
        "{%0,%1,%2,%3}, {%4,%5,%6,%7}, {%8,%9}, {%0,%1,%2,%3};"
        : "+f"(d0), "+f"(d1), "+f"(d2), "+f"(d3)
        : "r"(a0), "r"(a1), "r"(a2), "r"(a3), "r"(b0), "r"(b1));
}

// argmin key: truncate e mantissa low bits, pack col into low byte (ties -> lower col)
__device__ __forceinline__ uint32_t akey(float e, int col) {
    return (__float_as_uint(e) & 0xFFFFFF00u) | (uint32_t)col;
}

// k-permutation: within each 16-wide k-chunk, mma slot pairs of thread t4
// ({2t4,2t4+1} and {2t4+8,2t4+9}) hold global elements {4t4..4t4+3}.
// Applied consistently to A (float4 loads) and B (builder below).
// smem: per center n, 8 uint4 units. unit u=(kcp*4+t4)^((n&1)<<2) holds
// B' = -2*c fragments for k-chunks 2*kcp, 2*kcp+1. Conflict-free LDS.128.
struct SmemLayout {
    uint4 B[K_CENT * 8];    // 32 KB
    float c2[K_CENT];       // c2[n] + 1  (the "+1" of 1+d folded in)
};

__global__ __launch_bounds__(NTHREADS, 2)
void kmeans_hmma_kernel(const float* __restrict__ x,
                        const int*   __restrict__ y32,
                        const float* __restrict__ centers,
                        float* __restrict__ out) {
    extern __shared__ unsigned char s_raw[];
    SmemLayout* sm = reinterpret_cast<SmemLayout*>(s_raw);
    __shared__ int    s_hist[NUM_CLS * NUM_CLS];
    __shared__ double s_loss;
    __shared__ int    s_y_is32;
    __shared__ int    s_is_last;

    const int tid  = threadIdx.x;
    const int wid  = tid >> 5;
    const int lane = tid & 31;
    const int g    = lane >> 2;   // row within mma row-group (0..7)
    const int t4   = lane & 3;

    if (tid < NUM_CLS * NUM_CLS) s_hist[tid] = 0;
    if (tid == 0) s_loss = 0.0;
    // label dtype probe: int64 LE -> odd 32-bit words are all 0
    if (wid == 0) {
        int v = (y32[2 * (lane * 7 + 1) + 1] != 0) | (y32[2 * (lane + 64) + 1] != 0);
        uint32_t any = __ballot_sync(0xFFFFFFFFu, v);
        if (lane == 0) s_y_is32 = (any != 0);
    }

    // ---- build fp16 B' = -2*c fragments in smem (permuted k-order), once per CTA --
    for (int w = tid; w < K_CENT * 8; w += NTHREADS) {
        int n   = w >> 3;
        int u8  = w & 7;
        int kcp = u8 >> 2, tt = u8 & 3;
        const float* cn = centers + n * D_DIM;
        // chunk 2*kcp holds globals [kcp*32, kcp*32+16); slot tt -> globals +4*tt..+3
        float4 v0 = *(const float4*)(cn + kcp * 32 + tt * 4);        // chunk 2kcp
        float4 v1 = *(const float4*)(cn + kcp * 32 + 16 + tt * 4);   // chunk 2kcp+1
        int u = u8 ^ ((n & 1) << 2);
        sm->B[n * 8 + u] = make_uint4(h2(-2.f * v0.x, -2.f * v0.y),
                                      h2(-2.f * v0.z, -2.f * v0.w),
                                      h2(-2.f * v1.x, -2.f * v1.y),
                                      h2(-2.f * v1.z, -2.f * v1.w));
    }
    // center norms + 1 (fp32 exact)
    if (tid < K_CENT) {
        const float4* cp = (const float4*)(centers + tid * D_DIM);
        float a = 0.f;
        #pragma unroll
        for (int j = 0; j < 16; j++) {
            float4 v = cp[j];
            a = fmaf(v.x, v.x, a); a = fmaf(v.y, v.y, a);
            a = fmaf(v.z, v.z, a); a = fmaf(v.w, v.w, a);
        }
        sm->c2[tid] = a + 1.0f;
    }
    __syncthreads();
    const int y_is32 = s_y_is32;

    const uint4* Bbase = sm->B + g * 8;
    const int    uswz  = (g & 1) << 2;

    float loss_local = 0.f;

    for (int t = blockIdx.x; t < N_TILES; t += GRID_X) {
        const int r0 = t * TILE_M + wid * 16 + g;   // rows r0, r0+8
        const float* xr0 = x + (size_t)r0 * D_DIM + t4 * 4;
        const float* xr1 = xr0 + 8 * D_DIM;

        // ---- fp16 A fragments via ONE float4 per (row, k-chunk) + row norms ----
        uint32_t ah[4][4];
        float x2a = 0.f, x2b = 0.f;
        #pragma unroll
        for (int kc = 0; kc < 4; kc++) {
            float4 va = *(const float4*)(xr0 + kc * 16);
            float4 vb = *(const float4*)(xr1 + kc * 16);
            x2a = fmaf(va.x, va.x, x2a); x2a = fmaf(va.y, va.y, x2a);
            x2a = fmaf(va.z, va.z, x2a); x2a = fmaf(va.w, va.w, x2a);
            x2b = fmaf(vb.x, vb.x, x2b); x2b = fmaf(vb.y, vb.y, x2b);
            x2b = fmaf(vb.z, vb.z, x2b); x2b = fmaf(vb.w, vb.w, x2b);
            ah[kc][0] = h2(va.x, va.y);   // row r0, slots 2t4,2t4+1
            ah[kc][1] = h2(vb.x, vb.y);   // row r1, slots 2t4,2t4+1
            ah[kc][2] = h2(va.z, va.w);   // row r0, slots 2t4+8,2t4+9
            ah[kc][3] = h2(vb.z, vb.w);   // row r1, slots 2t4+8,2t4+9
        }
        x2a += __shfl_xor_sync(0xFFFFFFFFu, x2a, 1);
        x2a += __shfl_xor_sync(0xFFFFFFFFu, x2a, 2);
        x2b += __shfl_xor_sync(0xFFFFFFFFu, x2b, 1);
        x2b += __shfl_xor_sync(0xFFFFFFFFu, x2b, 2);

        float sw0 = 0.f, swe0 = 0.f, sw1 = 0.f, swe1 = 0.f;
        float dmin0 = FLT_MAX, dmin1 = FLT_MAX;
        float dmin10_0 = FLT_MAX, dmin10_1 = FLT_MAX;
        uint32_t key10_0 = 0xFFFFFFFFu, key10_1 = 0xFFFFFFFFu;

        // acc init = (x2 + c2 + 1); B' = -2c  =>  accumulator ends as e = 1 + d
        auto body = [&](int ng, bool track10) {
            const uint4* Bn = Bbase + ng * 64;
            uint4 bv0 = Bn[(0 + t4) ^ uswz];     // k-chunks 0,1
            uint4 bv1 = Bn[(4 + t4) ^ uswz];     // k-chunks 2,3
            float2 c2p = *(const float2*)(sm->c2 + ng * 8 + t4 * 2);
            float a0 = x2a + c2p.x, a1 = x2a + c2p.y;
            float a2 = x2b + c2p.x, a3 = x2b + c2p.y;
            mma_f16(a0, a1, a2, a3, ah[0][0], ah[0][1], ah[0][2], ah[0][3], bv0.x, bv0.y);
            mma_f16(a0, a1, a2, a3, ah[1][0], ah[1][1], ah[1][2], ah[1][3], bv0.z, bv0.w);
            mma_f16(a0, a1, a2, a3, ah[2][0], ah[2][1], ah[2][2], ah[2][3], bv1.x, bv1.y);
            mma_f16(a0, a1, a2, a3, ah[3][0], ah[3][1], ah[3][2], ah[3][3], bv1.z, bv1.w);
            float w0 = __powf(a0, -0.1f);
            float w1 = __powf(a1, -0.1f);
            float w2 = __powf(a2, -0.1f);
            float w3 = __powf(a3, -0.1f);
            sw0 += w0 + w1;
            sw1 += w2 + w3;
            swe0 = fmaf(w0, a0, swe0); swe0 = fmaf(w1, a1, swe0);
            swe1 = fmaf(w2, a2, swe1); swe1 = fmaf(w3, a3, swe1);
            dmin0 = fminf(dmin0, fminf(a0, a1));
            dmin1 = fminf(dmin1, fminf(a2, a3));
            if (track10) {
                // cols < 10 live only in ng=0 (cols 0-7) and ng=1/t4==0 (cols 8,9)
                if (ng == 0 || t4 == 0) {
                    const int cb = ng * 8 + t4 * 2;
                    key10_0 = min(key10_0, min(akey(a0, cb), akey(a1, cb + 1)));
                    key10_1 = min(key10_1, min(akey(a2, cb), akey(a3, cb + 1)));
                    dmin10_0 = fminf(dmin10_0, fminf(a0, a1));
                    dmin10_1 = fminf(dmin10_1, fminf(a2, a3));
                }
            }
        };
        body(0, true);
        body(1, true);
        #pragma unroll 6
        for (int ng = 2; ng < 32; ng++) body(ng, false);

        // quad reduction (4 lanes cover all 256 cols of rows r0, r0+8)
        #pragma unroll
        for (int off = 1; off <= 2; off <<= 1) {
            sw0  += __shfl_xor_sync(0xFFFFFFFFu, sw0,  off);
            swe0 += __shfl_xor_sync(0xFFFFFFFFu, swe0, off);
            sw1  += __shfl_xor_sync(0xFFFFFFFFu, sw1,  off);
            swe1 += __shfl_xor_sync(0xFFFFFFFFu, swe1, off);
            dmin0 = fminf(dmin0, __shfl_xor_sync(0xFFFFFFFFu, dmin0, off));
            dmin1 = fminf(dmin1, __shfl_xor_sync(0xFFFFFFFFu, dmin1, off));
            dmin10_0 = fminf(dmin10_0, __shfl_xor_sync(0xFFFFFFFFu, dmin10_0, off));
            dmin10_1 = fminf(dmin10_1, __shfl_xor_sync(0xFFFFFFFFu, dmin10_1, off));
            key10_0 = min(key10_0, __shfl_xor_sync(0xFFFFFFFFu, key10_0, off));
            key10_1 = min(key10_1, __shfl_xor_sync(0xFFFFFFFFu, key10_1, off));
        }

        if (t4 == 0) {
            loss_local += swe0 / sw0 + swe1 / sw1 - 2.0f;   // swe/sw - 1 per row
            // argmin < 10  <=>  min over cols<10 equals global min (ties -> lower col)
            if (dmin10_0 <= dmin0) {
                int lab = y_is32 ? y32[r0] : y32[2 * r0];
                atomicAdd_block(&s_hist[(int)(key10_0 & 0xFFu) * NUM_CLS + lab], 1);
            }
            if (dmin10_1 <= dmin1) {
                int r1 = r0 + 8;
                int lab = y_is32 ? y32[r1] : y32[2 * r1];
                atomicAdd_block(&s_hist[(int)(key10_1 & 0xFFu) * NUM_CLS + lab], 1);
            }
        }
    }

    // ---- flush per-CTA accumulators to global ----
    #pragma unroll
    for (int off = 16; off > 0; off >>= 1)
        loss_local += __shfl_xor_sync(0xFFFFFFFFu, loss_local, off);
    if (lane == 0) atomicAdd_block(&s_loss, (double)loss_local);
    __syncthreads();
    if (tid == 0) atomicAdd(&g_loss, s_loss);
    if (tid < NUM_CLS * NUM_CLS && s_hist[tid] > 0)
        atomicAdd(&g_counts[tid], s_hist[tid]);

    // ---- last-CTA fused finalize ----
    __threadfence();
    __syncthreads();
    if (tid == 0) {
        unsigned int prev = atomicAdd(&g_done, 1u);
        s_is_last = (prev == GRID_X - 1);
    }
    __syncthreads();
    if (!s_is_last || tid != 0) return;

    float counts[NUM_CLS * NUM_CLS];
    #pragma unroll
    for (int i = 0; i < NUM_CLS * NUM_CLS; i++)
        counts[i] = (float)atomicAdd(&g_counts[i], 0);

    bool used[NUM_CLS];
    #pragma unroll
    for (int i = 0; i < NUM_CLS; i++) used[i] = false;

    float correct = 0.f;
    for (int i = 0; i < NUM_CLS; i++) {
        const float* bin = &counts[i * NUM_CLS];
        float tot = 0.f;
        for (int j = 0; j < NUM_CLS; j++) tot += bin[j];
        int label = 0; float best = bin[0];
        for (int j = 1; j < NUM_CLS; j++)
            if (bin[j] > best) { best = bin[j]; label = j; }
        if (used[label]) {
            int l2 = 0; float b2 = used[0] ? 0.f : bin[0];
            for (int j = 1; j < NUM_CLS; j++) {
                float v = used[j] ? 0.f : bin[j];
                if (v > b2) { b2 = v; l2 = j; }
            }
            label = l2;
        }
        if (tot > 0.f) { correct += bin[label]; used[label] = true; }
    }
    out[0] = (float)g_loss;
    out[1] = correct / (float)N_ROWS;

    // reset globals so the next graph replay starts from a clean state
    g_loss = 0.0;
    #pragma unroll
    for (int i = 0; i < NUM_CLS * NUM_CLS; i++) g_counts[i] = 0;
    g_done = 0u;
}

// ---------------- launch ----------------
extern "C" void kernel_launch(void* const* d_in, const int* in_sizes, int n_in,
                              void* d_out, int out_size) {
    const float* x       = (const float*)d_in[0];
    const int*   y32     = (const int*)d_in[1];
    const float* centers = (const float*)d_in[2];

    const int dyn_smem = (int)sizeof(SmemLayout);
    cudaFuncSetAttribute(kmeans_hmma_kernel,
                         cudaFuncAttributeMaxDynamicSharedMemorySize, dyn_smem);

    kmeans_hmma_kernel<<<GRID_X, NTHREADS, dyn_smem>>>(x, y32, centers, (float*)d_out);
}